// round 10
// baseline (speedup 1.0000x reference)
#include <cuda_runtime.h>
#include <cuda_fp16.h>
#include <cstdint>

#define NTT   365
#define NGRID 2048
#define NX    16
#define NH    256
#define NG    1024
#define ROWS  (NTT*NGRID)      /* 747520 */
#define CELLS 32
#define NBLK  (NGRID/CELLS)    /* 64 */

// ---------------------------------------------------------------------------
// Device-global scratch (~1.54 GB total; must stay < 2 GB for host link)
// ---------------------------------------------------------------------------
__device__ __half g_xg[(size_t)ROWS * NG];   // 1.53 GB fp16 xg for ALL steps
__device__ uint4 g_qih[NG * 32];             // fp16 w_ih records [n][kb2][t] (512KB)
__device__ uint4 g_qhh[NG * 32];             // fp16 w_hh records [n][kb2][t] (512KB)
__device__ float g_bias2[NG];

// ---------------------------------------------------------------------------
// PTX helpers (sm_100 baseline-safe: mma.sync / ldmatrix / cp.async / tanh.approx)
// ---------------------------------------------------------------------------
__device__ __forceinline__ uint32_t su32(const void* p) {
    uint32_t a;
    asm("{ .reg .u64 t; cvta.to.shared.u64 t, %1; cvt.u32.u64 %0, t; }" : "=r"(a) : "l"(p));
    return a;
}
__device__ __forceinline__ void mma_f16(float& c0, float& c1, float& c2, float& c3,
                                        uint32_t a0, uint32_t a1, uint32_t a2, uint32_t a3,
                                        uint32_t b0, uint32_t b1) {
    asm volatile(
        "mma.sync.aligned.m16n8k16.row.col.f32.f16.f16.f32 "
        "{%0,%1,%2,%3},{%4,%5,%6,%7},{%8,%9},{%0,%1,%2,%3};"
        : "+f"(c0), "+f"(c1), "+f"(c2), "+f"(c3)
        : "r"(a0), "r"(a1), "r"(a2), "r"(a3), "r"(b0), "r"(b1));
}
__device__ __forceinline__ void ldmat4(uint32_t* r, uint32_t addr) {
    asm volatile("ldmatrix.sync.aligned.m8n8.x4.shared.b16 {%0,%1,%2,%3},[%4];"
                 : "=r"(r[0]), "=r"(r[1]), "=r"(r[2]), "=r"(r[3]) : "r"(addr));
}
__device__ __forceinline__ void cpa16(uint32_t s, const void* g) {
    asm volatile("cp.async.cg.shared.global [%0],[%1],16;" :: "r"(s), "l"(g));
}
#define CPA_COMMIT() asm volatile("cp.async.commit_group;" ::: "memory")
#define CPA_WAIT0()  asm volatile("cp.async.wait_group 0;" ::: "memory")

__device__ __forceinline__ uint32_t pkh2(float a, float b) {
    __half2 h = __floats2half2_rn(a, b);
    return *(uint32_t*)&h;
}
__device__ __forceinline__ float sigf(float x)  { return __fdividef(1.f, 1.f + __expf(-x)); }
__device__ __forceinline__ float tanha(float x) {
    float y; asm("tanh.approx.f32 %0, %1;" : "=f"(y) : "f"(x)); return y;
}

// ---------------------------------------------------------------------------
// Kernel 0: pack fp16 weight records + fold bias.
// record (n, kb2, t): 16B uint4 covering kb=2*kb2, 2*kb2+1 for lane t; layout
// [n][kb2][t] -> quad t-lanes contiguous (coalesced), 1 LDG.128 = 2 k-steps.
// ---------------------------------------------------------------------------
__global__ void prep_kernel(const float* __restrict__ w_ih, const float* __restrict__ w_hh,
                            const float* __restrict__ b_ih, const float* __restrict__ b_hh) {
    int idx = blockIdx.x * blockDim.x + threadIdx.x;   // 32768
    if (idx >= NG * 32) return;
    int n = idx >> 5, kb2 = (idx >> 2) & 7, t = idx & 3;
    int k0 = kb2 * 32 + 2 * t;
#pragma unroll
    for (int w = 0; w < 2; w++) {
        const float* src = (w ? w_hh : w_ih) + n * NH;
        uint4 q;
        q.x = pkh2(src[k0],      src[k0 + 1]);
        q.y = pkh2(src[k0 + 8],  src[k0 + 9]);
        q.z = pkh2(src[k0 + 16], src[k0 + 17]);
        q.w = pkh2(src[k0 + 24], src[k0 + 25]);
        (w ? g_qhh : g_qih)[idx] = q;
    }
    if (idx < NG) g_bias2[idx] = b_ih[idx] + b_hh[idx];
}

// ---------------------------------------------------------------------------
// Kernel 1: fused input + xg GEMM (single-term fp16 mma.sync). Unchanged R9.
// ---------------------------------------------------------------------------
#define A_TILE (128 * 528)                        /* 67584 */
#define G_SMEM (A_TILE + 8192 + 256 * 17 * 4)     /* 93184 */

__global__ void __launch_bounds__(512, 1) xg_gemm_kernel(const float* __restrict__ x,
                                                         const float* __restrict__ w_in,
                                                         const float* __restrict__ b_in) {
    extern __shared__ char sm[];
    char*  A0 = sm;
    float* xs = (float*)(sm + A_TILE);             // [128][16]
    float* ws = (float*)(sm + A_TILE + 8192);      // [256][17], last = bias
    int tid = threadIdx.x, lane = tid & 31, w = tid >> 5;
    int wm = w >> 2, wn = w & 3;
    int g = lane >> 2, t = lane & 3;
    size_t m0 = (size_t)blockIdx.x * 128;

    ((uint4*)xs)[tid] = ((const uint4*)(x + m0 * NX))[tid];
    {
        int h = tid >> 1, i0 = (tid & 1) * 8;
        const float* src = w_in + h * NX + i0;
#pragma unroll
        for (int i = 0; i < 8; i++) ws[h * 17 + i0 + i] = src[i];
        if ((tid & 1) == 0) ws[h * 17 + 16] = b_in[h];
    }
    __syncthreads();

    for (int it = 0; it < 64; it++) {
        int idx = it * 512 + tid, r = idx >> 8, h = idx & 255;
        float acc = ws[h * 17 + 16];
#pragma unroll
        for (int i = 0; i < 16; i++) acc += xs[r * 16 + i] * ws[h * 17 + i];
        *(__half*)(A0 + r * 528 + h * 2) = __float2half(fmaxf(acc, 0.f));
    }
    __syncthreads();

    uint32_t lbase = (uint32_t)((wm * 32 + (lane & 15)) * 528 + (lane >> 4) * 16);
    uint32_t a0b = su32(A0) + lbase;

    for (int nt = 0; nt < 8; nt++) {
        float acc[2][4][4];
#pragma unroll
        for (int mt = 0; mt < 2; mt++)
#pragma unroll
            for (int nb = 0; nb < 4; nb++)
#pragma unroll
                for (int r = 0; r < 4; r++) acc[mt][nb][r] = 0.f;

        unsigned bofs[4];
#pragma unroll
        for (int nb = 0; nb < 4; nb++)
            bofs[nb] = (unsigned)((nt * 128 + wn * 32 + nb * 8 + g) * 32 + t);

#pragma unroll
        for (int kb = 0; kb < 16; kb += 2) {
            uint32_t af[2][4], ag[2][4];
#pragma unroll
            for (int mt = 0; mt < 2; mt++) {
                ldmat4(af[mt], a0b + mt * 16 * 528 + kb * 32);
                ldmat4(ag[mt], a0b + mt * 16 * 528 + (kb + 1) * 32);
            }
            uint4 Bq[4];
#pragma unroll
            for (int nb = 0; nb < 4; nb++)
                Bq[nb] = g_qih[bofs[nb] + (kb >> 1) * 4];
#pragma unroll
            for (int mt = 0; mt < 2; mt++)
#pragma unroll
                for (int nb = 0; nb < 4; nb++) {
                    mma_f16(acc[mt][nb][0], acc[mt][nb][1], acc[mt][nb][2], acc[mt][nb][3],
                            af[mt][0], af[mt][1], af[mt][2], af[mt][3], Bq[nb].x, Bq[nb].y);
                    mma_f16(acc[mt][nb][0], acc[mt][nb][1], acc[mt][nb][2], acc[mt][nb][3],
                            ag[mt][0], ag[mt][1], ag[mt][2], ag[mt][3], Bq[nb].z, Bq[nb].w);
                }
        }

#pragma unroll
        for (int nb = 0; nb < 4; nb++) {
            int col = nt * 128 + wn * 32 + nb * 8 + 2 * t;
            float2 bs = *(const float2*)(g_bias2 + col);
#pragma unroll
            for (int mt = 0; mt < 2; mt++) {
                size_t row = m0 + wm * 32 + mt * 16 + g;
                *(__half2*)(g_xg + row * NG + col) =
                    __floats2half2_rn(acc[mt][nb][0] + bs.x, acc[mt][nb][1] + bs.y);
                *(__half2*)(g_xg + (row + 8) * NG + col) =
                    __floats2half2_rn(acc[mt][nb][2] + bs.x, acc[mt][nb][3] + bs.y);
            }
        }
    }
}

// ---------------------------------------------------------------------------
// Kernel 2: full 365-step scan, 64 CTAs x 32 cells x 512 thr (16 warps).
// Warp w owns hidden [16w,16w+16) over all 4 gate groups; M=32 via 2 m-tiles.
// c-state in smem (reg relief). Weight traffic halves chip-wide vs 128 CTAs.
// ---------------------------------------------------------------------------
#define XROW 2064                        /* fp16 xg row stride (bytes) */
#define XGB  (CELLS * XROW)              /* 66048 */
#define S_HS (2 * XGB)                   /* 132096 */
#define HSB  (CELLS * 528)               /* 16896: one fp16 h tile (32 rows) */
#define S_CST (S_HS + 2 * HSB)           /* 165888 */
#define S_RED (S_CST + 16 * 512 * 4)     /* 198656 */
#define S_SMEM (S_RED + 2048)            /* 200704 */

__global__ void __launch_bounds__(512, 1) lstm_scan(const float* __restrict__ w_out,
                                                    const float* __restrict__ b_out,
                                                    float* __restrict__ out) {
    extern __shared__ char sm[];
    float* cst = (float*)(sm + S_CST);   // [16][512] thread-major
    float* red = (float*)(sm + S_RED);   // [32 cells][16 warps]
    int tid = threadIdx.x, lane = tid & 31, w = tid >> 5;
    int g = lane >> 2, t = lane & 3;
    int b0 = blockIdx.x * CELLS;

    // zero h buffer 0 + c-state
    for (int i = tid; i < HSB / 4; i += 512) ((uint32_t*)(sm + S_HS))[i] = 0;
#pragma unroll
    for (int i = 0; i < 16; i++) cst[i * 512 + tid] = 0.f;

    // prefetch xg step 0 (32 cells x 2048B = 64KB)
    {
        const char* src = (const char*)(g_xg + (size_t)b0 * NG);
        uint32_t dst = su32(sm);
        for (int c = tid; c < 4096; c += 512)
            cpa16(dst + (c >> 7) * XROW + (c & 127) * 16, src + c * 16);
        CPA_COMMIT();
    }

    float2 wo[2];
#pragma unroll
    for (int nb = 0; nb < 2; nb++) wo[nb] = *(const float2*)(w_out + w * 16 + nb * 8 + 2 * t);
    float bout = b_out[0];

    unsigned bofs[4][2];
#pragma unroll
    for (int G = 0; G < 4; G++)
#pragma unroll
        for (int nb = 0; nb < 2; nb++)
            bofs[G][nb] = (unsigned)((G * 256 + w * 16 + nb * 8 + g) * 32 + t);

    uint32_t hlbase = (uint32_t)((lane & 15) * 528 + (lane >> 4) * 16);

    for (int st = 0; st < NTT; st++) {
        CPA_WAIT0();
        __syncthreads();
        int rb = st & 1, wb = rb ^ 1;

        // accumulator init = xg (fp16 -> f32)
        char* xb = sm + rb * XGB;
        float acc[4][2][2][4];       // [G][mt][nb][r]
#pragma unroll
        for (int G = 0; G < 4; G++)
#pragma unroll
            for (int mt = 0; mt < 2; mt++)
#pragma unroll
                for (int nb = 0; nb < 2; nb++) {
                    int col = G * 256 + w * 16 + nb * 8 + 2 * t;
                    float2 f01 = __half22float2(*(__half2*)(xb + (mt * 16 + g) * XROW + col * 2));
                    float2 f23 = __half22float2(*(__half2*)(xb + (mt * 16 + g + 8) * XROW + col * 2));
                    acc[G][mt][nb][0] = f01.x; acc[G][mt][nb][1] = f01.y;
                    acc[G][mt][nb][2] = f23.x; acc[G][mt][nb][3] = f23.y;
                }

        // prefetch next step's xg
        if (st + 1 < NTT) {
            const char* src = (const char*)(g_xg + ((size_t)(st + 1) * NGRID + b0) * NG);
            uint32_t dst = su32(sm) + wb * XGB;
            for (int c = tid; c < 4096; c += 512)
                cpa16(dst + (c >> 7) * XROW + (c & 127) * 16, src + c * 16);
        }
        CPA_COMMIT();

        // h(prev) @ w_hh^T over K=256, M=32 (2 m-tiles), fp16
        uint32_t h0b = su32(sm) + S_HS + rb * HSB + hlbase;
#pragma unroll
        for (int kb = 0; kb < 16; kb += 2) {
            uint32_t a[2][2][4];
#pragma unroll
            for (int mt = 0; mt < 2; mt++) {
                ldmat4(a[mt][0], h0b + mt * 16 * 528 + kb * 32);
                ldmat4(a[mt][1], h0b + mt * 16 * 528 + (kb + 1) * 32);
            }
#pragma unroll
            for (int Gh = 0; Gh < 2; Gh++) {
                uint4 B[2][2];
#pragma unroll
                for (int Gi = 0; Gi < 2; Gi++)
#pragma unroll
                    for (int nb = 0; nb < 2; nb++)
                        B[Gi][nb] = g_qhh[bofs[Gh * 2 + Gi][nb] + (kb >> 1) * 4];
#pragma unroll
                for (int Gi = 0; Gi < 2; Gi++)
#pragma unroll
                    for (int mt = 0; mt < 2; mt++)
#pragma unroll
                        for (int nb = 0; nb < 2; nb++) {
                            float* c4 = acc[Gh * 2 + Gi][mt][nb];
                            mma_f16(c4[0], c4[1], c4[2], c4[3],
                                    a[mt][0][0], a[mt][0][1], a[mt][0][2], a[mt][0][3],
                                    B[Gi][nb].x, B[Gi][nb].y);
                            mma_f16(c4[0], c4[1], c4[2], c4[3],
                                    a[mt][1][0], a[mt][1][1], a[mt][1][2], a[mt][1][3],
                                    B[Gi][nb].z, B[Gi][nb].w);
                        }
            }
        }

        // pointwise cell + h restage + fused output partials
        char* hw0 = sm + S_HS + wb * HSB;
        float p[4] = {0.f, 0.f, 0.f, 0.f};   // partials for cells g, g+8, 16+g, 24+g
#pragma unroll
        for (int mt = 0; mt < 2; mt++)
#pragma unroll
            for (int nb = 0; nb < 2; nb++) {
                int j0 = w * 16 + nb * 8 + 2 * t;
#pragma unroll
                for (int rh = 0; rh < 2; rh++) {      // row-half: g / g+8
                    int r0 = rh * 2;
                    int row = mt * 16 + rh * 8 + g;
                    int ci = ((mt * 2 + rh) * 2 + nb) * 2;
                    float i0 = sigf(acc[0][mt][nb][r0]),     f0 = sigf(acc[1][mt][nb][r0]);
                    float g0 = tanha(acc[2][mt][nb][r0]),    o0 = sigf(acc[3][mt][nb][r0]);
                    float i1 = sigf(acc[0][mt][nb][r0 + 1]), f1 = sigf(acc[1][mt][nb][r0 + 1]);
                    float g1 = tanha(acc[2][mt][nb][r0 + 1]), o1 = sigf(acc[3][mt][nb][r0 + 1]);
                    float cA = f0 * cst[ci * 512 + tid] + i0 * g0;
                    float cB = f1 * cst[(ci + 1) * 512 + tid] + i1 * g1;
                    cst[ci * 512 + tid] = cA;
                    cst[(ci + 1) * 512 + tid] = cB;
                    float hA = o0 * tanha(cA), hB = o1 * tanha(cB);
                    p[mt * 2 + rh] += hA * wo[nb].x + hB * wo[nb].y;
                    *(uint32_t*)(hw0 + row * 528 + j0 * 2) = pkh2(hA, hB);
                }
            }
#pragma unroll
        for (int q = 0; q < 4; q++) {
            p[q] += __shfl_xor_sync(0xffffffffu, p[q], 1);
            p[q] += __shfl_xor_sync(0xffffffffu, p[q], 2);
        }
        if (t == 0) {
            red[(g)      * 16 + w] = p[0];
            red[(g + 8)  * 16 + w] = p[1];
            red[(g + 16) * 16 + w] = p[2];
            red[(g + 24) * 16 + w] = p[3];
        }
        __syncthreads();
        if (tid < 32) {
            float s = bout;
#pragma unroll
            for (int k = 0; k < 16; k++) s += red[tid * 16 + k];
            out[(size_t)st * NGRID + b0 + tid] = s;
        }
    }
}

// ---------------------------------------------------------------------------
extern "C" void kernel_launch(void* const* d_in, const int* in_sizes, int n_in,
                              void* d_out, int out_size) {
    const float* x     = (const float*)d_in[0];
    const float* w_in  = (const float*)d_in[1];
    const float* b_in  = (const float*)d_in[2];
    const float* w_ih  = (const float*)d_in[3];
    const float* w_hh  = (const float*)d_in[4];
    const float* b_ih  = (const float*)d_in[5];
    const float* b_hh  = (const float*)d_in[6];
    const float* w_out = (const float*)d_in[7];
    const float* b_out = (const float*)d_in[8];
    float* out = (float*)d_out;

    cudaFuncSetAttribute(xg_gemm_kernel, cudaFuncAttributeMaxDynamicSharedMemorySize, G_SMEM);
    cudaFuncSetAttribute(lstm_scan,      cudaFuncAttributeMaxDynamicSharedMemorySize, S_SMEM);

    prep_kernel<<<(NG * 32 + 255) / 256, 256>>>(w_ih, w_hh, b_ih, b_hh);
    xg_gemm_kernel<<<ROWS / 128, 512, G_SMEM>>>(x, w_in, b_in);
    lstm_scan<<<NBLK, 512, S_SMEM>>>(w_out, b_out, out);
}

// round 12
// speedup vs baseline: 1.3306x; 1.3306x over previous
#include <cuda_runtime.h>
#include <cuda_fp16.h>
#include <cstdint>

#define NTT   365
#define NGRID 2048
#define NX    16
#define NH    256
#define NG    1024
#define CELLS 16
#define NBLK  (NGRID/CELLS)    /* 128 */
#define ROWS  (NTT*NGRID)      /* 747520 */

// ---------------------------------------------------------------------------
// Device-global scratch (~1.54 GB total; must stay < 2 GB for host link)
// ---------------------------------------------------------------------------
__device__ __half g_xg[(size_t)ROWS * NG];   // 1.53 GB fp16 xg for ALL steps
__device__ uint4 g_qih[NG * 32];             // fp16 w_ih records [n][kb2][t] (512KB)
__device__ uint4 g_qhh[NG * 32];             // fp16 w_hh records [n][kb2][t] (512KB)
__device__ float g_bias2[NG];

// ---------------------------------------------------------------------------
// PTX helpers (sm_100 baseline-safe)
// ---------------------------------------------------------------------------
__device__ __forceinline__ uint32_t su32(const void* p) {
    uint32_t a;
    asm("{ .reg .u64 t; cvta.to.shared.u64 t, %1; cvt.u32.u64 %0, t; }" : "=r"(a) : "l"(p));
    return a;
}
__device__ __forceinline__ void mma_f16(float& c0, float& c1, float& c2, float& c3,
                                        uint32_t a0, uint32_t a1, uint32_t a2, uint32_t a3,
                                        uint32_t b0, uint32_t b1) {
    asm volatile(
        "mma.sync.aligned.m16n8k16.row.col.f32.f16.f16.f32 "
        "{%0,%1,%2,%3},{%4,%5,%6,%7},{%8,%9},{%0,%1,%2,%3};"
        : "+f"(c0), "+f"(c1), "+f"(c2), "+f"(c3)
        : "r"(a0), "r"(a1), "r"(a2), "r"(a3), "r"(b0), "r"(b1));
}
__device__ __forceinline__ void ldmat4(uint32_t* r, uint32_t addr) {
    asm volatile("ldmatrix.sync.aligned.m8n8.x4.shared.b16 {%0,%1,%2,%3},[%4];"
                 : "=r"(r[0]), "=r"(r[1]), "=r"(r[2]), "=r"(r[3]) : "r"(addr));
}
__device__ __forceinline__ void cpa16(uint32_t s, const void* g) {
    asm volatile("cp.async.cg.shared.global [%0],[%1],16;" :: "r"(s), "l"(g));
}
#define CPA_COMMIT() asm volatile("cp.async.commit_group;" ::: "memory")
#define CPA_WAIT0()  asm volatile("cp.async.wait_group 0;" ::: "memory")

__device__ __forceinline__ uint32_t pkh2(float a, float b) {
    __half2 h = __floats2half2_rn(a, b);
    return *(uint32_t*)&h;
}
__device__ __forceinline__ float tanha(float x) {
    float y; asm("tanh.approx.f32 %0, %1;" : "=f"(y) : "f"(x)); return y;
}
// sigmoid via tanh.approx: 1 MUFU instead of 2 (R10 showed tanh.approx is
// rel_err-neutral at this problem's scale)
__device__ __forceinline__ float sigf(float x) {
    return fmaf(tanha(0.5f * x), 0.5f, 0.5f);
}

// ---------------------------------------------------------------------------
// Kernel 0: pack fp16 weight records + fold bias. Record (n,kb2,t): 16B uint4
// covering kb=2*kb2, 2*kb2+1 for lane t; [n][kb2][t] -> quad-coalesced.
// ---------------------------------------------------------------------------
__global__ void prep_kernel(const float* __restrict__ w_ih, const float* __restrict__ w_hh,
                            const float* __restrict__ b_ih, const float* __restrict__ b_hh) {
    int idx = blockIdx.x * blockDim.x + threadIdx.x;   // 32768
    if (idx >= NG * 32) return;
    int n = idx >> 5, kb2 = (idx >> 2) & 7, t = idx & 3;
    int k0 = kb2 * 32 + 2 * t;
#pragma unroll
    for (int w = 0; w < 2; w++) {
        const float* src = (w ? w_hh : w_ih) + n * NH;
        uint4 q;
        q.x = pkh2(src[k0],      src[k0 + 1]);
        q.y = pkh2(src[k0 + 8],  src[k0 + 9]);
        q.z = pkh2(src[k0 + 16], src[k0 + 17]);
        q.w = pkh2(src[k0 + 24], src[k0 + 25]);
        (w ? g_qhh : g_qih)[idx] = q;
    }
    if (idx < NG) g_bias2[idx] = b_ih[idx] + b_hh[idx];
}

// ---------------------------------------------------------------------------
// Kernel 1: fused input + xg GEMM (single-term fp16 mma.sync). R9-identical.
// ---------------------------------------------------------------------------
#define A_TILE (128 * 528)                        /* 67584 */
#define G_SMEM (A_TILE + 8192 + 256 * 17 * 4)     /* 93184 */

__global__ void __launch_bounds__(512, 1) xg_gemm_kernel(const float* __restrict__ x,
                                                         const float* __restrict__ w_in,
                                                         const float* __restrict__ b_in) {
    extern __shared__ char sm[];
    char*  A0 = sm;
    float* xs = (float*)(sm + A_TILE);             // [128][16]
    float* ws = (float*)(sm + A_TILE + 8192);      // [256][17], last = bias
    int tid = threadIdx.x, lane = tid & 31, w = tid >> 5;
    int wm = w >> 2, wn = w & 3;
    int g = lane >> 2, t = lane & 3;
    size_t m0 = (size_t)blockIdx.x * 128;

    ((uint4*)xs)[tid] = ((const uint4*)(x + m0 * NX))[tid];
    {
        int h = tid >> 1, i0 = (tid & 1) * 8;
        const float* src = w_in + h * NX + i0;
#pragma unroll
        for (int i = 0; i < 8; i++) ws[h * 17 + i0 + i] = src[i];
        if ((tid & 1) == 0) ws[h * 17 + 16] = b_in[h];
    }
    __syncthreads();

    for (int it = 0; it < 64; it++) {
        int idx = it * 512 + tid, r = idx >> 8, h = idx & 255;
        float acc = ws[h * 17 + 16];
#pragma unroll
        for (int i = 0; i < 16; i++) acc += xs[r * 16 + i] * ws[h * 17 + i];
        *(__half*)(A0 + r * 528 + h * 2) = __float2half(fmaxf(acc, 0.f));
    }
    __syncthreads();

    uint32_t lbase = (uint32_t)((wm * 32 + (lane & 15)) * 528 + (lane >> 4) * 16);
    uint32_t a0b = su32(A0) + lbase;

    for (int nt = 0; nt < 8; nt++) {
        float acc[2][4][4];
#pragma unroll
        for (int mt = 0; mt < 2; mt++)
#pragma unroll
            for (int nb = 0; nb < 4; nb++)
#pragma unroll
                for (int r = 0; r < 4; r++) acc[mt][nb][r] = 0.f;

        unsigned bofs[4];
#pragma unroll
        for (int nb = 0; nb < 4; nb++)
            bofs[nb] = (unsigned)((nt * 128 + wn * 32 + nb * 8 + g) * 32 + t);

#pragma unroll
        for (int kb = 0; kb < 16; kb += 2) {
            uint32_t af[2][4], ag[2][4];
#pragma unroll
            for (int mt = 0; mt < 2; mt++) {
                ldmat4(af[mt], a0b + mt * 16 * 528 + kb * 32);
                ldmat4(ag[mt], a0b + mt * 16 * 528 + (kb + 1) * 32);
            }
            uint4 Bq[4];
#pragma unroll
            for (int nb = 0; nb < 4; nb++)
                Bq[nb] = g_qih[bofs[nb] + (kb >> 1) * 4];
#pragma unroll
            for (int mt = 0; mt < 2; mt++)
#pragma unroll
                for (int nb = 0; nb < 4; nb++) {
                    mma_f16(acc[mt][nb][0], acc[mt][nb][1], acc[mt][nb][2], acc[mt][nb][3],
                            af[mt][0], af[mt][1], af[mt][2], af[mt][3], Bq[nb].x, Bq[nb].y);
                    mma_f16(acc[mt][nb][0], acc[mt][nb][1], acc[mt][nb][2], acc[mt][nb][3],
                            ag[mt][0], ag[mt][1], ag[mt][2], ag[mt][3], Bq[nb].z, Bq[nb].w);
                }
        }

#pragma unroll
        for (int nb = 0; nb < 4; nb++) {
            int col = nt * 128 + wn * 32 + nb * 8 + 2 * t;
            float2 bs = *(const float2*)(g_bias2 + col);
#pragma unroll
            for (int mt = 0; mt < 2; mt++) {
                size_t row = m0 + wm * 32 + mt * 16 + g;
                *(__half2*)(g_xg + row * NG + col) =
                    __floats2half2_rn(acc[mt][nb][0] + bs.x, acc[mt][nb][1] + bs.y);
                *(__half2*)(g_xg + (row + 8) * NG + col) =
                    __floats2half2_rn(acc[mt][nb][2] + bs.x, acc[mt][nb][3] + bs.y);
            }
        }
    }
}

// ---------------------------------------------------------------------------
// Kernel 2: full 365-step scan (R9 config: 128 CTAs x 16 cells x 512 thr),
// with software-pipelined weight loads and tanh-based sigmoid.
// ---------------------------------------------------------------------------
#define XROW 2064                       /* fp16 xg row stride (bytes) */
#define XGB  (16 * XROW)                /* 33024 */
#define S_HS (2 * XGB)                  /* 66048 */
#define HSB  (16 * 528)                 /* 8448: one fp16 h tile */
#define S_RED (S_HS + 2 * HSB)          /* 82944 */
#define S_SMEM (S_RED + 1024)           /* 83968 */

__global__ void __launch_bounds__(512, 1) lstm_scan(const float* __restrict__ w_out,
                                                    const float* __restrict__ b_out,
                                                    float* __restrict__ out) {
    extern __shared__ char sm[];
    float* red = (float*)(sm + S_RED);
    int tid = threadIdx.x, lane = tid & 31, w = tid >> 5;
    int g = lane >> 2, t = lane & 3;
    int b0 = blockIdx.x * CELLS;

    // zero h tile (buffer 0); c-state in regs
    for (int i = tid; i < (2 * HSB) / 4; i += 512) ((uint32_t*)(sm + S_HS))[i] = 0;
    float cst[8];
#pragma unroll
    for (int i = 0; i < 8; i++) cst[i] = 0.f;

    // prefetch xg step 0 (16 cells x 2048B = 32KB)
    {
        const char* src = (const char*)(g_xg + (size_t)b0 * NG);
        uint32_t dst = su32(sm);
        for (int c = tid; c < 2048; c += 512)
            cpa16(dst + (c >> 7) * XROW + (c & 127) * 16, src + c * 16);
        CPA_COMMIT();
    }

    float2 wo[2];
#pragma unroll
    for (int nb = 0; nb < 2; nb++) wo[nb] = *(const float2*)(w_out + w * 16 + nb * 8 + 2 * t);
    float bout = b_out[0];

    unsigned bofs[4][2];
#pragma unroll
    for (int G = 0; G < 4; G++)
#pragma unroll
        for (int nb = 0; nb < 2; nb++)
            bofs[G][nb] = (unsigned)((G * 256 + w * 16 + nb * 8 + g) * 32 + t);

    uint32_t hlbase = (uint32_t)((lane & 15) * 528 + (lane >> 4) * 16);

    for (int st = 0; st < NTT; st++) {
        CPA_WAIT0();
        __syncthreads();
        int rb = st & 1, wb = rb ^ 1;

        // issue first weight-load group (G0,G1 @ kb2=0) BEFORE xg init so the
        // L2 latency overlaps the 16 LDS + cvt of accumulator init.
        uint4 Bp[2][2];
#pragma unroll
        for (int Gi = 0; Gi < 2; Gi++)
#pragma unroll
            for (int nb = 0; nb < 2; nb++)
                Bp[Gi][nb] = g_qhh[bofs[Gi][nb]];

        // accumulator init = xg (fp16 -> f32)
        char* xb = sm + rb * XGB;
        float acc[4][2][4];
#pragma unroll
        for (int G = 0; G < 4; G++)
#pragma unroll
            for (int nb = 0; nb < 2; nb++) {
                int col = G * 256 + w * 16 + nb * 8 + 2 * t;
                float2 f01 = __half22float2(*(__half2*)(xb + g * XROW + col * 2));
                float2 f23 = __half22float2(*(__half2*)(xb + (g + 8) * XROW + col * 2));
                acc[G][nb][0] = f01.x; acc[G][nb][1] = f01.y;
                acc[G][nb][2] = f23.x; acc[G][nb][3] = f23.y;
            }

        // prefetch next step's xg
        if (st + 1 < NTT) {
            const char* src = (const char*)(g_xg + ((size_t)(st + 1) * NGRID + b0) * NG);
            uint32_t dst = su32(sm) + wb * XGB;
            for (int c = tid; c < 2048; c += 512)
                cpa16(dst + (c >> 7) * XROW + (c & 127) * 16, src + c * 16);
        }
        CPA_COMMIT();

        // h(prev) @ w_hh^T over K=256, fp16, pipelined B loads:
        // always issue the NEXT group's 4 LDG.128 before consuming the current.
        uint32_t h0b = su32(sm) + S_HS + rb * HSB + hlbase;
#pragma unroll
        for (int kb2 = 0; kb2 < 8; kb2++) {
            uint32_t a0[4], a1[4];
            ldmat4(a0, h0b + (2 * kb2) * 32);
            ldmat4(a1, h0b + (2 * kb2 + 1) * 32);
            // issue G2,G3 loads for this kb2
            uint4 Bq[2][2];
#pragma unroll
            for (int Gi = 0; Gi < 2; Gi++)
#pragma unroll
                for (int nb = 0; nb < 2; nb++)
                    Bq[Gi][nb] = g_qhh[bofs[2 + Gi][nb] + kb2 * 4];
            // consume G0,G1 (loaded one half-iteration ago)
#pragma unroll
            for (int Gi = 0; Gi < 2; Gi++)
#pragma unroll
                for (int nb = 0; nb < 2; nb++) {
                    float* c4 = acc[Gi][nb];
                    mma_f16(c4[0], c4[1], c4[2], c4[3],
                            a0[0], a0[1], a0[2], a0[3], Bp[Gi][nb].x, Bp[Gi][nb].y);
                    mma_f16(c4[0], c4[1], c4[2], c4[3],
                            a1[0], a1[1], a1[2], a1[3], Bp[Gi][nb].z, Bp[Gi][nb].w);
                }
            // issue G0,G1 loads for kb2+1
            if (kb2 < 7) {
#pragma unroll
                for (int Gi = 0; Gi < 2; Gi++)
#pragma unroll
                    for (int nb = 0; nb < 2; nb++)
                        Bp[Gi][nb] = g_qhh[bofs[Gi][nb] + (kb2 + 1) * 4];
            }
            // consume G2,G3
#pragma unroll
            for (int Gi = 0; Gi < 2; Gi++)
#pragma unroll
                for (int nb = 0; nb < 2; nb++) {
                    float* c4 = acc[2 + Gi][nb];
                    mma_f16(c4[0], c4[1], c4[2], c4[3],
                            a0[0], a0[1], a0[2], a0[3], Bq[Gi][nb].x, Bq[Gi][nb].y);
                    mma_f16(c4[0], c4[1], c4[2], c4[3],
                            a1[0], a1[1], a1[2], a1[3], Bq[Gi][nb].z, Bq[Gi][nb].w);
                }
        }

        // pointwise cell + h restage + fused output partials
        char* hw0 = sm + S_HS + wb * HSB;
        float p0 = 0.f, p1 = 0.f;
#pragma unroll
        for (int nb = 0; nb < 2; nb++) {
            int j0 = w * 16 + nb * 8 + 2 * t;
            {   // cell g (regs 0,1)
                float i0 = sigf(acc[0][nb][0]), f0 = sigf(acc[1][nb][0]);
                float g0 = tanha(acc[2][nb][0]), o0 = sigf(acc[3][nb][0]);
                float i1 = sigf(acc[0][nb][1]), f1 = sigf(acc[1][nb][1]);
                float g1 = tanha(acc[2][nb][1]), o1 = sigf(acc[3][nb][1]);
                float& cA = cst[nb * 4 + 0]; cA = f0 * cA + i0 * g0;
                float& cB = cst[nb * 4 + 1]; cB = f1 * cB + i1 * g1;
                float hA = o0 * tanha(cA), hB = o1 * tanha(cB);
                p0 += hA * wo[nb].x + hB * wo[nb].y;
                *(uint32_t*)(hw0 + g * 528 + j0 * 2) = pkh2(hA, hB);
            }
            {   // cell g+8 (regs 2,3)
                float i0 = sigf(acc[0][nb][2]), f0 = sigf(acc[1][nb][2]);
                float g0 = tanha(acc[2][nb][2]), o0 = sigf(acc[3][nb][2]);
                float i1 = sigf(acc[0][nb][3]), f1 = sigf(acc[1][nb][3]);
                float g1 = tanha(acc[2][nb][3]), o1 = sigf(acc[3][nb][3]);
                float& cA = cst[nb * 4 + 2]; cA = f0 * cA + i0 * g0;
                float& cB = cst[nb * 4 + 3]; cB = f1 * cB + i1 * g1;
                float hA = o0 * tanha(cA), hB = o1 * tanha(cB);
                p1 += hA * wo[nb].x + hB * wo[nb].y;
                *(uint32_t*)(hw0 + (g + 8) * 528 + j0 * 2) = pkh2(hA, hB);
            }
        }
        p0 += __shfl_xor_sync(0xffffffffu, p0, 1);
        p0 += __shfl_xor_sync(0xffffffffu, p0, 2);
        p1 += __shfl_xor_sync(0xffffffffu, p1, 1);
        p1 += __shfl_xor_sync(0xffffffffu, p1, 2);
        if (t == 0) { red[g * 16 + w] = p0; red[(g + 8) * 16 + w] = p1; }
        __syncthreads();
        if (tid < 16) {
            float s = bout;
#pragma unroll
            for (int k = 0; k < 16; k++) s += red[tid * 16 + k];
            out[(size_t)st * NGRID + b0 + tid] = s;
        }
    }
}

// ---------------------------------------------------------------------------
extern "C" void kernel_launch(void* const* d_in, const int* in_sizes, int n_in,
                              void* d_out, int out_size) {
    const float* x     = (const float*)d_in[0];
    const float* w_in  = (const float*)d_in[1];
    const float* b_in  = (const float*)d_in[2];
    const float* w_ih  = (const float*)d_in[3];
    const float* w_hh  = (const float*)d_in[4];
    const float* b_ih  = (const float*)d_in[5];
    const float* b_hh  = (const float*)d_in[6];
    const float* w_out = (const float*)d_in[7];
    const float* b_out = (const float*)d_in[8];
    float* out = (float*)d_out;

    cudaFuncSetAttribute(xg_gemm_kernel, cudaFuncAttributeMaxDynamicSharedMemorySize, G_SMEM);
    cudaFuncSetAttribute(lstm_scan,      cudaFuncAttributeMaxDynamicSharedMemorySize, S_SMEM);

    prep_kernel<<<(NG * 32 + 255) / 256, 256>>>(w_ih, w_hh, b_ih, b_hh);
    xg_gemm_kernel<<<ROWS / 128, 512, G_SMEM>>>(x, w_in, b_in);
    lstm_scan<<<NBLK, 512, S_SMEM>>>(w_out, b_out, out);
}

// round 14
// speedup vs baseline: 1.5219x; 1.1438x over previous
#include <cuda_runtime.h>
#include <cuda_fp16.h>
#include <cstdint>

#define NTT   365
#define NGRID 2048
#define NX    16
#define NH    256
#define NG    1024
#define CELLS 16
#define NBLK  (NGRID/CELLS)    /* 128 */
#define ROWS  (NTT*NGRID)      /* 747520 */

// ---------------------------------------------------------------------------
// Device-global scratch (~1.54 GB total; must stay < 2 GB for host link)
// ---------------------------------------------------------------------------
__device__ __half g_xg[(size_t)ROWS * NG];   // 1.53 GB fp16 xg for ALL steps
__device__ uint4 g_qih[NG * 32];             // w_ih records [n][kb2][t]   (512KB)
__device__ uint4 g_qhh[NG * 32];             // w_hh records [kb2][n][t]   (512KB)
__device__ float g_bias2[NG];

// ---------------------------------------------------------------------------
// PTX helpers (sm_100 baseline-safe)
// ---------------------------------------------------------------------------
__device__ __forceinline__ uint32_t su32(const void* p) {
    uint32_t a;
    asm("{ .reg .u64 t; cvta.to.shared.u64 t, %1; cvt.u32.u64 %0, t; }" : "=r"(a) : "l"(p));
    return a;
}
__device__ __forceinline__ void mma_f16(float& c0, float& c1, float& c2, float& c3,
                                        uint32_t a0, uint32_t a1, uint32_t a2, uint32_t a3,
                                        uint32_t b0, uint32_t b1) {
    asm volatile(
        "mma.sync.aligned.m16n8k16.row.col.f32.f16.f16.f32 "
        "{%0,%1,%2,%3},{%4,%5,%6,%7},{%8,%9},{%0,%1,%2,%3};"
        : "+f"(c0), "+f"(c1), "+f"(c2), "+f"(c3)
        : "r"(a0), "r"(a1), "r"(a2), "r"(a3), "r"(b0), "r"(b1));
}
__device__ __forceinline__ void ldmat4(uint32_t* r, uint32_t addr) {
    asm volatile("ldmatrix.sync.aligned.m8n8.x4.shared.b16 {%0,%1,%2,%3},[%4];"
                 : "=r"(r[0]), "=r"(r[1]), "=r"(r[2]), "=r"(r[3]) : "r"(addr));
}
__device__ __forceinline__ void cpa16(uint32_t s, const void* g) {
    asm volatile("cp.async.cg.shared.global [%0],[%1],16;" :: "r"(s), "l"(g));
}
#define CPA_COMMIT() asm volatile("cp.async.commit_group;" ::: "memory")
template<int N> __device__ __forceinline__ void cpa_wait() {
    asm volatile("cp.async.wait_group %0;" :: "n"(N) : "memory");
}

__device__ __forceinline__ uint32_t pkh2(float a, float b) {
    __half2 h = __floats2half2_rn(a, b);
    return *(uint32_t*)&h;
}
__device__ __forceinline__ float tanha(float x) {
    float y; asm("tanh.approx.f32 %0, %1;" : "=f"(y) : "f"(x)); return y;
}
__device__ __forceinline__ float sigf(float x) {
    return fmaf(tanha(0.5f * x), 0.5f, 0.5f);
}

// ---------------------------------------------------------------------------
// Kernel 0: pack fp16 weight records + fold bias.
// qih: [n][kb2][t] (consumed by GEMM via coalesced LDG.128)
// qhh: [kb2][n][t] (64KB contiguous per kb2 -> cp.async stage copies)
// record (n,kb2,t): 16B uint4 covering kb=2*kb2, 2*kb2+1 for lane t.
// ---------------------------------------------------------------------------
__global__ void prep_kernel(const float* __restrict__ w_ih, const float* __restrict__ w_hh,
                            const float* __restrict__ b_ih, const float* __restrict__ b_hh) {
    int idx = blockIdx.x * blockDim.x + threadIdx.x;   // 32768
    if (idx >= NG * 32) return;
    int n = idx >> 5, kb2 = (idx >> 2) & 7, t = idx & 3;
    int k0 = kb2 * 32 + 2 * t;
#pragma unroll
    for (int w = 0; w < 2; w++) {
        const float* src = (w ? w_hh : w_ih) + n * NH;
        uint4 q;
        q.x = pkh2(src[k0],      src[k0 + 1]);
        q.y = pkh2(src[k0 + 8],  src[k0 + 9]);
        q.z = pkh2(src[k0 + 16], src[k0 + 17]);
        q.w = pkh2(src[k0 + 24], src[k0 + 25]);
        if (w) g_qhh[kb2 * 4096 + n * 4 + t] = q;
        else   g_qih[idx] = q;
    }
    if (idx < NG) g_bias2[idx] = b_ih[idx] + b_hh[idx];
}

// ---------------------------------------------------------------------------
// Kernel 1: fused input + xg GEMM (single-term fp16 mma.sync). R12-identical.
// ---------------------------------------------------------------------------
#define A_TILE (128 * 528)                        /* 67584 */
#define G_SMEM (A_TILE + 8192 + 256 * 17 * 4)     /* 93184 */

__global__ void __launch_bounds__(512, 1) xg_gemm_kernel(const float* __restrict__ x,
                                                         const float* __restrict__ w_in,
                                                         const float* __restrict__ b_in) {
    extern __shared__ char sm[];
    char*  A0 = sm;
    float* xs = (float*)(sm + A_TILE);             // [128][16]
    float* ws = (float*)(sm + A_TILE + 8192);      // [256][17], last = bias
    int tid = threadIdx.x, lane = tid & 31, w = tid >> 5;
    int wm = w >> 2, wn = w & 3;
    int g = lane >> 2, t = lane & 3;
    size_t m0 = (size_t)blockIdx.x * 128;

    ((uint4*)xs)[tid] = ((const uint4*)(x + m0 * NX))[tid];
    {
        int h = tid >> 1, i0 = (tid & 1) * 8;
        const float* src = w_in + h * NX + i0;
#pragma unroll
        for (int i = 0; i < 8; i++) ws[h * 17 + i0 + i] = src[i];
        if ((tid & 1) == 0) ws[h * 17 + 16] = b_in[h];
    }
    __syncthreads();

    for (int it = 0; it < 64; it++) {
        int idx = it * 512 + tid, r = idx >> 8, h = idx & 255;
        float acc = ws[h * 17 + 16];
#pragma unroll
        for (int i = 0; i < 16; i++) acc += xs[r * 16 + i] * ws[h * 17 + i];
        *(__half*)(A0 + r * 528 + h * 2) = __float2half(fmaxf(acc, 0.f));
    }
    __syncthreads();

    uint32_t lbase = (uint32_t)((wm * 32 + (lane & 15)) * 528 + (lane >> 4) * 16);
    uint32_t a0b = su32(A0) + lbase;

    for (int nt = 0; nt < 8; nt++) {
        float acc[2][4][4];
#pragma unroll
        for (int mt = 0; mt < 2; mt++)
#pragma unroll
            for (int nb = 0; nb < 4; nb++)
#pragma unroll
                for (int r = 0; r < 4; r++) acc[mt][nb][r] = 0.f;

        unsigned bofs[4];
#pragma unroll
        for (int nb = 0; nb < 4; nb++)
            bofs[nb] = (unsigned)((nt * 128 + wn * 32 + nb * 8 + g) * 32 + t);

#pragma unroll
        for (int kb = 0; kb < 16; kb += 2) {
            uint32_t af[2][4], ag[2][4];
#pragma unroll
            for (int mt = 0; mt < 2; mt++) {
                ldmat4(af[mt], a0b + mt * 16 * 528 + kb * 32);
                ldmat4(ag[mt], a0b + mt * 16 * 528 + (kb + 1) * 32);
            }
            uint4 Bq[4];
#pragma unroll
            for (int nb = 0; nb < 4; nb++)
                Bq[nb] = g_qih[bofs[nb] + (kb >> 1) * 4];
#pragma unroll
            for (int mt = 0; mt < 2; mt++)
#pragma unroll
                for (int nb = 0; nb < 4; nb++) {
                    mma_f16(acc[mt][nb][0], acc[mt][nb][1], acc[mt][nb][2], acc[mt][nb][3],
                            af[mt][0], af[mt][1], af[mt][2], af[mt][3], Bq[nb].x, Bq[nb].y);
                    mma_f16(acc[mt][nb][0], acc[mt][nb][1], acc[mt][nb][2], acc[mt][nb][3],
                            ag[mt][0], ag[mt][1], ag[mt][2], ag[mt][3], Bq[nb].z, Bq[nb].w);
                }
        }

#pragma unroll
        for (int nb = 0; nb < 4; nb++) {
            int col = nt * 128 + wn * 32 + nb * 8 + 2 * t;
            float2 bs = *(const float2*)(g_bias2 + col);
#pragma unroll
            for (int mt = 0; mt < 2; mt++) {
                size_t row = m0 + wm * 32 + mt * 16 + g;
                *(__half2*)(g_xg + row * NG + col) =
                    __floats2half2_rn(acc[mt][nb][0] + bs.x, acc[mt][nb][1] + bs.y);
                *(__half2*)(g_xg + (row + 8) * NG + col) =
                    __floats2half2_rn(acc[mt][nb][2] + bs.x, acc[mt][nb][3] + bs.y);
            }
        }
    }
}

// ---------------------------------------------------------------------------
// Kernel 2: full 365-step scan, 128 CTAs x 16 cells x 512 thr (16 warps).
// Weights stream via cp.async into per-warp 2x4KB smem ping-pong slots:
// full L2-latency hiding with zero register cost, no cross-warp hazards
// (each thread copies exactly the records it consumes).
// ---------------------------------------------------------------------------
#define XROW 2064                       /* fp16 xg row stride (bytes) */
#define XGB  (16 * XROW)                /* 33024 */
#define S_HS (2 * XGB)                  /* 66048 */
#define HSB  (16 * 528)                 /* 8448: one fp16 h tile */
#define S_RED (S_HS + 2 * HSB)          /* 82944 */
#define S_W   (S_RED + 1024)            /* 83968: weight stages */
#define S_SMEM (S_W + 16 * 2 * 4096)    /* 215040 */

__global__ void __launch_bounds__(512, 1) lstm_scan(const float* __restrict__ w_out,
                                                    const float* __restrict__ b_out,
                                                    float* __restrict__ out) {
    extern __shared__ char sm[];
    float* red = (float*)(sm + S_RED);
    int tid = threadIdx.x, lane = tid & 31, w = tid >> 5;
    int g = lane >> 2, t = lane & 3;
    int b0 = blockIdx.x * CELLS;

    // zero h tile (buffer 0); c-state in regs
    for (int i = tid; i < (2 * HSB) / 4; i += 512) ((uint32_t*)(sm + S_HS))[i] = 0;
    float cst[8];
#pragma unroll
    for (int i = 0; i < 8; i++) cst[i] = 0.f;

    // per-warp weight stage bases
    uint32_t wsb = su32(sm) + S_W + w * 8192;        // smem addr of slot 0
    const char* wsm = sm + S_W + w * 8192;           // generic ptr for LDS
    // gmem chunk offsets (uint4 index within a kb2 block): chunk j=(G,nb)
    unsigned cb[8];
#pragma unroll
    for (int j = 0; j < 8; j++)
        cb[j] = (unsigned)((j >> 1) * 1024 + w * 64 + (j & 1) * 32 + lane);

#define W_COPY(slot, kb2s) do { \
    _Pragma("unroll") \
    for (int j = 0; j < 8; j++) \
        cpa16(wsb + (slot) * 4096 + j * 512 + lane * 16, \
              (const void*)(g_qhh + (kb2s) * 4096 + cb[j])); \
    CPA_COMMIT(); } while (0)

    // prefetch xg step 0 (16 cells x 2048B = 32KB)
    {
        const char* src = (const char*)(g_xg + (size_t)b0 * NG);
        uint32_t dst = su32(sm);
        for (int c = tid; c < 2048; c += 512)
            cpa16(dst + (c >> 7) * XROW + (c & 127) * 16, src + c * 16);
        CPA_COMMIT();
    }

    float2 wo[2];
#pragma unroll
    for (int nb = 0; nb < 2; nb++) wo[nb] = *(const float2*)(w_out + w * 16 + nb * 8 + 2 * t);
    float bout = b_out[0];

    uint32_t hlbase = (uint32_t)((lane & 15) * 528 + (lane >> 4) * 16);

    for (int st = 0; st < NTT; st++) {
        cpa_wait<0>();       // drains this step's xg (and anything stale)
        __syncthreads();
        int rb = st & 1, wb = rb ^ 1;

        // start weight pipeline for this step
        W_COPY(0, 0);
        W_COPY(1, 1);

        // accumulator init = xg (fp16 -> f32)
        char* xb = sm + rb * XGB;
        float acc[4][2][4];
#pragma unroll
        for (int G = 0; G < 4; G++)
#pragma unroll
            for (int nb = 0; nb < 2; nb++) {
                int col = G * 256 + w * 16 + nb * 8 + 2 * t;
                float2 f01 = __half22float2(*(__half2*)(xb + g * XROW + col * 2));
                float2 f23 = __half22float2(*(__half2*)(xb + (g + 8) * XROW + col * 2));
                acc[G][nb][0] = f01.x; acc[G][nb][1] = f01.y;
                acc[G][nb][2] = f23.x; acc[G][nb][3] = f23.y;
            }

        uint32_t h0b = su32(sm) + S_HS + rb * HSB + hlbase;

#define KB_CONSUME(kb2c, WGN) do { \
    uint32_t a0[4], a1[4]; \
    ldmat4(a0, h0b + (2 * (kb2c)) * 32); \
    ldmat4(a1, h0b + (2 * (kb2c) + 1) * 32); \
    cpa_wait<WGN>(); \
    const char* wslot = wsm + ((kb2c) & 1) * 4096; \
    _Pragma("unroll") \
    for (int G = 0; G < 4; G++) \
    _Pragma("unroll") \
    for (int nb = 0; nb < 2; nb++) { \
        uint4 Bq = *(const uint4*)(wslot + (G * 2 + nb) * 512 + lane * 16); \
        float* c4 = acc[G][nb]; \
        mma_f16(c4[0], c4[1], c4[2], c4[3], a0[0], a0[1], a0[2], a0[3], Bq.x, Bq.y); \
        mma_f16(c4[0], c4[1], c4[2], c4[3], a1[0], a1[1], a1[2], a1[3], Bq.z, Bq.w); \
    } } while (0)

        // commit order: W0,W1,[k0]W2,[k1]W3,X,[k2]W4,[k3]W5,[k4]W6,[k5]W7
        KB_CONSUME(0, 1);  W_COPY(0, 2);
        KB_CONSUME(1, 1);  W_COPY(1, 3);
        // prefetch next step's xg (always issue; dummy reload on last step)
        {
            int pf = (st + 1 < NTT) ? st + 1 : st;
            const char* src = (const char*)(g_xg + ((size_t)pf * NGRID + b0) * NG);
            uint32_t dst = su32(sm) + wb * XGB;
            for (int c = tid; c < 2048; c += 512)
                cpa16(dst + (c >> 7) * XROW + (c & 127) * 16, src + c * 16);
            CPA_COMMIT();
        }
        KB_CONSUME(2, 2);  W_COPY(0, 4);
        KB_CONSUME(3, 2);  W_COPY(1, 5);
        KB_CONSUME(4, 1);  W_COPY(0, 6);
        KB_CONSUME(5, 1);  W_COPY(1, 7);
        KB_CONSUME(6, 1);
        KB_CONSUME(7, 0);
#undef KB_CONSUME

        // pointwise cell + h restage + fused output partials
        char* hw0 = sm + S_HS + wb * HSB;
        float p0 = 0.f, p1 = 0.f;
#pragma unroll
        for (int nb = 0; nb < 2; nb++) {
            int j0 = w * 16 + nb * 8 + 2 * t;
            {   // cell g (regs 0,1)
                float i0 = sigf(acc[0][nb][0]), f0 = sigf(acc[1][nb][0]);
                float g0 = tanha(acc[2][nb][0]), o0 = sigf(acc[3][nb][0]);
                float i1 = sigf(acc[0][nb][1]), f1 = sigf(acc[1][nb][1]);
                float g1 = tanha(acc[2][nb][1]), o1 = sigf(acc[3][nb][1]);
                float& cA = cst[nb * 4 + 0]; cA = f0 * cA + i0 * g0;
                float& cB = cst[nb * 4 + 1]; cB = f1 * cB + i1 * g1;
                float hA = o0 * tanha(cA), hB = o1 * tanha(cB);
                p0 += hA * wo[nb].x + hB * wo[nb].y;
                *(uint32_t*)(hw0 + g * 528 + j0 * 2) = pkh2(hA, hB);
            }
            {   // cell g+8 (regs 2,3)
                float i0 = sigf(acc[0][nb][2]), f0 = sigf(acc[1][nb][2]);
                float g0 = tanha(acc[2][nb][2]), o0 = sigf(acc[3][nb][2]);
                float i1 = sigf(acc[0][nb][3]), f1 = sigf(acc[1][nb][3]);
                float g1 = tanha(acc[2][nb][3]), o1 = sigf(acc[3][nb][3]);
                float& cA = cst[nb * 4 + 2]; cA = f0 * cA + i0 * g0;
                float& cB = cst[nb * 4 + 3]; cB = f1 * cB + i1 * g1;
                float hA = o0 * tanha(cA), hB = o1 * tanha(cB);
                p1 += hA * wo[nb].x + hB * wo[nb].y;
                *(uint32_t*)(hw0 + (g + 8) * 528 + j0 * 2) = pkh2(hA, hB);
            }
        }
        p0 += __shfl_xor_sync(0xffffffffu, p0, 1);
        p0 += __shfl_xor_sync(0xffffffffu, p0, 2);
        p1 += __shfl_xor_sync(0xffffffffu, p1, 1);
        p1 += __shfl_xor_sync(0xffffffffu, p1, 2);
        if (t == 0) { red[g * 16 + w] = p0; red[(g + 8) * 16 + w] = p1; }
        __syncthreads();
        if (tid < 16) {
            float s = bout;
#pragma unroll
            for (int k = 0; k < 16; k++) s += red[tid * 16 + k];
            out[(size_t)st * NGRID + b0 + tid] = s;
        }
    }
#undef W_COPY
}

// ---------------------------------------------------------------------------
extern "C" void kernel_launch(void* const* d_in, const int* in_sizes, int n_in,
                              void* d_out, int out_size) {
    const float* x     = (const float*)d_in[0];
    const float* w_in  = (const float*)d_in[1];
    const float* b_in  = (const float*)d_in[2];
    const float* w_ih  = (const float*)d_in[3];
    const float* w_hh  = (const float*)d_in[4];
    const float* b_ih  = (const float*)d_in[5];
    const float* b_hh  = (const float*)d_in[6];
    const float* w_out = (const float*)d_in[7];
    const float* b_out = (const float*)d_in[8];
    float* out = (float*)d_out;

    cudaFuncSetAttribute(xg_gemm_kernel, cudaFuncAttributeMaxDynamicSharedMemorySize, G_SMEM);
    cudaFuncSetAttribute(lstm_scan,      cudaFuncAttributeMaxDynamicSharedMemorySize, S_SMEM);

    prep_kernel<<<(NG * 32 + 255) / 256, 256>>>(w_ih, w_hh, b_ih, b_hh);
    xg_gemm_kernel<<<ROWS / 128, 512, G_SMEM>>>(x, w_in, b_in);
    lstm_scan<<<NBLK, 512, S_SMEM>>>(w_out, b_out, out);
}